// round 11
// baseline (speedup 1.0000x reference)
#include <cuda_runtime.h>
#include <cuda_bf16.h>
#include <math.h>
#include <cstdint>

#define Bb 16
#define Cc 512
#define Hh 32
#define Ww 32
#define Nn 16384
#define Dd 32
#define Pp 16384   // Bb*Hh*Ww

// ---------------------------------------------------------------------------
// Scratch (__device__ globals; no allocation allowed)
// ---------------------------------------------------------------------------
__device__ float g_z[Pp * Dd];        // normalized projected latents [p][d]
__device__ float g_e[Nn * Dd];        // normalized codebook fp32 [n][d] (rows 128B aligned)
__device__ uint4 g_eb[Nn * 8];        // codebook bf16 split: [n][64 bf16] = [hi|mid]
__device__ float g_tmax[(size_t)Pp * 512];  // per-position per-32-code-entry max
__device__ int   g_idx[Pp];
__device__ int   g_hist[Nn];
__device__ float g_loss_part[512];

// ---------------------------------------------------------------------------
// PTX helpers (baseline PTX only: no 'a'-features)
// ---------------------------------------------------------------------------
__device__ __forceinline__ uint32_t smem_u32(const void* p) {
    uint32_t a;
    asm("{ .reg .u64 t; cvta.to.shared.u64 t, %1; cvt.u32.u64 %0, t; }" : "=r"(a) : "l"(p));
    return a;
}
__device__ __forceinline__ void ldsm4(uint32_t* r, uint32_t addr) {
    asm volatile("ldmatrix.sync.aligned.m8n8.x4.shared.b16 {%0,%1,%2,%3}, [%4];"
                 : "=r"(r[0]), "=r"(r[1]), "=r"(r[2]), "=r"(r[3]) : "r"(addr));
}
__device__ __forceinline__ void mma16816(float* d, const uint32_t* a, const uint32_t* b) {
    asm volatile("mma.sync.aligned.m16n8k16.row.col.f32.bf16.bf16.f32 "
                 "{%0,%1,%2,%3}, {%4,%5,%6,%7}, {%8,%9}, {%0,%1,%2,%3};"
                 : "+f"(d[0]), "+f"(d[1]), "+f"(d[2]), "+f"(d[3])
                 : "r"(a[0]), "r"(a[1]), "r"(a[2]), "r"(a[3]), "r"(b[0]), "r"(b[1]));
}
__device__ __forceinline__ void cpasync16(uint32_t dst, const void* src) {
    asm volatile("cp.async.cg.shared.global [%0], [%1], 16;" :: "r"(dst), "l"(src));
}
#define CP_COMMIT() asm volatile("cp.async.commit_group;" ::: "memory")
#define CP_WAIT0()  asm volatile("cp.async.wait_group 0;" ::: "memory")

__device__ __forceinline__ bool better(float xv, int xi, float yv, int yi) {
    return xv > yv || (xv == yv && xi < yi);
}

// ---------------------------------------------------------------------------
// K_zero: clear histogram (also shifts k_sims into the ncu capture slot)
// ---------------------------------------------------------------------------
__global__ void k_zero_hist() {
    g_hist[blockIdx.x * 256 + threadIdx.x] = 0;
}

// ---------------------------------------------------------------------------
// K_prep_e: normalize codebook rows; fp32 copy + bf16 split [hi|mid].
// ---------------------------------------------------------------------------
__global__ void k_prep_e(const float* __restrict__ emb) {
    int warp = threadIdx.x >> 5, lane = threadIdx.x & 31;
    int n = blockIdx.x * 8 + warp;
    float v = emb[n * Dd + lane];
    float ss = v * v;
    #pragma unroll
    for (int o = 16; o; o >>= 1) ss += __shfl_xor_sync(0xffffffffu, ss, o);
    float rn = 1.0f / fmaxf(sqrtf(ss), 1e-6f);
    float zn = v * rn;
    g_e[n * Dd + lane] = zn;

    __nv_bfloat16 h = __float2bfloat16(zn);
    __nv_bfloat16 m = __float2bfloat16(zn - __bfloat162float(h));
    __nv_bfloat16* gb = (__nv_bfloat16*)g_eb + (size_t)n * 64 + lane;
    gb[0]  = h;    // k-block 0: e_hi
    gb[32] = m;    // k-block 1: e_mid
}

// ---------------------------------------------------------------------------
// K1: projection (1x1 conv C->D) + L2 normalize along D.
// ---------------------------------------------------------------------------
__global__ __launch_bounds__(256) void k_project(const float* __restrict__ enc,
                                                 const float* __restrict__ pw,
                                                 const float* __restrict__ pb) {
    __shared__ float enc_s[64][32];
    __shared__ float proj_s[32][64];
    __shared__ float z_s[32][33];
    __shared__ float rn_s[32];

    int bh  = blockIdx.x;
    int tid = threadIdx.x;
    int w   = tid & 31;
    int dg  = tid >> 5;

    const float* encbase = enc + (size_t)(bh >> 5) * Cc * Hh * Ww + (size_t)(bh & 31) * Ww;

    float acc[4] = {0.f, 0.f, 0.f, 0.f};

    for (int c0 = 0; c0 < Cc; c0 += 64) {
        #pragma unroll
        for (int k = 0; k < 2; k++) {
            int i = tid + 256 * k;            // 0..511
            int cl = i >> 3, v = i & 7;
            *(float4*)&enc_s[cl][v * 4] =
                *(const float4*)(encbase + (size_t)(c0 + cl) * (Hh * Ww) + v * 4);
        }
        #pragma unroll
        for (int k = 0; k < 2; k++) {
            int i = tid + 256 * k;
            int d = i >> 4, c4 = i & 15;
            *(float4*)&proj_s[d][c4 * 4] =
                *(const float4*)(pw + d * Cc + c0 + c4 * 4);
        }
        __syncthreads();
        #pragma unroll 16
        for (int cl = 0; cl < 64; cl++) {
            float ev = enc_s[cl][w];
            #pragma unroll
            for (int j = 0; j < 4; j++) acc[j] += proj_s[dg + 8 * j][cl] * ev;
        }
        __syncthreads();
    }
    #pragma unroll
    for (int j = 0; j < 4; j++) z_s[dg + 8 * j][w] = acc[j] + pb[dg + 8 * j];
    __syncthreads();

    if (tid < 32) {
        float ss = 0.f;
        #pragma unroll
        for (int d = 0; d < 32; d++) { float v = z_s[d][tid]; ss += v * v; }
        rn_s[tid] = 1.0f / fmaxf(sqrtf(ss), 1e-6f);
    }
    __syncthreads();

    for (int i = tid; i < 1024; i += 256) {
        int ww = i >> 5, d = i & 31;
        g_z[((size_t)bh * 32 + ww) * Dd + d] = z_s[d][ww] * rn_s[ww];
    }
}

// ---------------------------------------------------------------------------
// K2: HMMA sims (bf16 3-split via B-fragment reuse, K_smem=64);
// per-position per-32-code-entry MAX only.
// CTA: 256 threads (8 warps), 64 positions; 2 CTAs/SM. Code tile = 128.
// Warp: rg = w&3 (16 positions), nh = w>>2 (64 codes).
// NEW: 4 B buffers, tiles processed in PAIRS — one CP_WAIT0 + one
// __syncthreads per 2 tiles (barrier count halved, 2 tiles of independent
// MMA work per sync section). Pair prefetch targets the buffers of tiles
// t2-2/t2-1, which this pair's barrier has just proven drained.
// ---------------------------------------------------------------------------
#define A_BYTES   9216                        // 64 * 144
#define B_BYTES   18432                       // 128 * 144
#define SIMS_SMEM (A_BYTES + 4 * B_BYTES)     // 82944

__global__ __launch_bounds__(256, 2) void k_sims() {
    extern __shared__ __align__(16) char sm[];
    __nv_bfloat16* As = (__nv_bfloat16*)sm;   // stride 72 bf16 = 144 B
    uint32_t sbase = smem_u32(sm);

    int tid  = threadIdx.x;
    int lane = tid & 31;
    int w    = tid >> 5;      // 0..7
    int rg   = w & 3;         // row group (16 positions)
    int nh   = w >> 2;        // n-half (64 codes)
    int tg   = lane & 3;
    int gr   = lane >> 2;     // row-in-group 0..7
    int pbase = blockIdx.x * 64;

    // ---- build A tile: [hi | mid] per row (64 rows, 144 B stride) ----
    for (int i = tid; i < 64 * 32; i += 256) {
        int row = i >> 5, d = i & 31;
        float z = g_z[(size_t)(pbase + row) * Dd + d];
        __nv_bfloat16 h = __float2bfloat16(z);
        __nv_bfloat16 m = __float2bfloat16(z - __bfloat162float(h));
        As[row * 72 + d]      = h;
        As[row * 72 + 32 + d] = m;
    }

    // ---- cp.async addressing: row = tid>>1, 4 chunks of 16B per thread ----
    uint32_t cprow = (uint32_t)(tid >> 1);
    uint32_t cphalf = (uint32_t)((tid & 1) * 64);
    uint32_t srcBase = cprow * 128 + cphalf;
    uint32_t dstBase = cprow * 144 + cphalf;

    // ---- prefetch B tiles 0 and 1 (one group) ----
    const char* ebase = (const char*)g_eb;
    #pragma unroll
    for (int j = 0; j < 4; j++)
        cpasync16(sbase + A_BYTES + dstBase + j * 16, ebase + srcBase + j * 16);
    #pragma unroll
    for (int j = 0; j < 4; j++)
        cpasync16(sbase + A_BYTES + B_BYTES + dstBase + j * 16,
                  ebase + 16384 + srcBase + j * 16);
    CP_COMMIT();
    __syncthreads();

    // ---- A fragments: 4 k-steps (zh: 0,1; zm: 2,3), hoisted (16 regs) ----
    uint32_t afr[4][4];
    int q = lane >> 3, r = lane & 7;
    {
        uint32_t abase = sbase + (uint32_t)((rg * 16 + (q & 1) * 8 + r) * 144
                                            + (q >> 1) * 16);
        #pragma unroll
        for (int kk = 0; kk < 4; kk++) ldsm4(afr[kk], abase + kk * 32);
    }
    uint32_t brow_off = (uint32_t)((nh * 64 + (q >> 1) * 8 + r) * 144 + (q & 1) * 16);

    for (int t2 = 0; t2 < 128; t2 += 2) {
        CP_WAIT0();
        __syncthreads();
        if (t2 + 2 < 128) {
            // prefetch pair (t2+2, t2+3) -> buffers (t2+2)&3, (t2+3)&3
            const char* s0 = ebase + (size_t)(t2 + 2) * 16384 + srcBase;
            uint32_t d0 = sbase + A_BYTES + (uint32_t)(((t2 + 2) & 3) * B_BYTES) + dstBase;
            #pragma unroll
            for (int j = 0; j < 4; j++) cpasync16(d0 + j * 16, s0 + j * 16);
            const char* s1 = ebase + (size_t)(t2 + 3) * 16384 + srcBase;
            uint32_t d1 = sbase + A_BYTES + (uint32_t)(((t2 + 3) & 3) * B_BYTES) + dstBase;
            #pragma unroll
            for (int j = 0; j < 4; j++) cpasync16(d1 + j * 16, s1 + j * 16);
            CP_COMMIT();
        }

        #pragma unroll 1
        for (int u = 0; u < 2; u++) {
            int t = t2 + u;
            uint32_t bb = sbase + A_BYTES + (uint32_t)((t & 3) * B_BYTES) + brow_off;
            float acc[8][4];
            #pragma unroll
            for (int nb = 0; nb < 8; nb++)
                #pragma unroll
                for (int i = 0; i < 4; i++) acc[nb][i] = 0.f;

            #pragma unroll
            for (int j = 0; j < 4; j++) {          // four n16 groups
                uint32_t bbj = bb + (uint32_t)j * (16 * 144);
                uint32_t beh0[4], beh1[4], bem0[4], bem1[4];
                ldsm4(beh0, bbj);                  // eh, k-step 0
                ldsm4(beh1, bbj + 32);             // eh, k-step 1
                ldsm4(bem0, bbj + 64);             // em, k-step 0
                ldsm4(bem1, bbj + 96);             // em, k-step 1
                // zh*eh
                mma16816(acc[2*j],   afr[0], beh0); mma16816(acc[2*j+1], afr[0], beh0 + 2);
                mma16816(acc[2*j],   afr[1], beh1); mma16816(acc[2*j+1], afr[1], beh1 + 2);
                // zh*em
                mma16816(acc[2*j],   afr[0], bem0); mma16816(acc[2*j+1], afr[0], bem0 + 2);
                mma16816(acc[2*j],   afr[1], bem1); mma16816(acc[2*j+1], afr[1], bem1 + 2);
                // zm*eh (reuses eh fragments — no extra LDSM)
                mma16816(acc[2*j],   afr[2], beh0); mma16816(acc[2*j+1], afr[2], beh0 + 2);
                mma16816(acc[2*j],   afr[3], beh1); mma16816(acc[2*j+1], afr[3], beh1 + 2);
            }

            // ---- per-entry max (value only, FMNMX trees + shfl) ----
            float mA0, mA1, mB0, mB1;
            {
                float a0 = fmaxf(fmaxf(acc[0][0], acc[0][1]), fmaxf(acc[1][0], acc[1][1]));
                float a1 = fmaxf(fmaxf(acc[2][0], acc[2][1]), fmaxf(acc[3][0], acc[3][1]));
                mA0 = fmaxf(a0, a1);
                float a2 = fmaxf(fmaxf(acc[4][0], acc[4][1]), fmaxf(acc[5][0], acc[5][1]));
                float a3 = fmaxf(fmaxf(acc[6][0], acc[6][1]), fmaxf(acc[7][0], acc[7][1]));
                mA1 = fmaxf(a2, a3);
                float b0 = fmaxf(fmaxf(acc[0][2], acc[0][3]), fmaxf(acc[1][2], acc[1][3]));
                float b1 = fmaxf(fmaxf(acc[2][2], acc[2][3]), fmaxf(acc[3][2], acc[3][3]));
                mB0 = fmaxf(b0, b1);
                float b2 = fmaxf(fmaxf(acc[4][2], acc[4][3]), fmaxf(acc[5][2], acc[5][3]));
                float b3 = fmaxf(fmaxf(acc[6][2], acc[6][3]), fmaxf(acc[7][2], acc[7][3]));
                mB1 = fmaxf(b2, b3);
            }
            mA0 = fmaxf(mA0, __shfl_xor_sync(0xffffffffu, mA0, 1));
            mA0 = fmaxf(mA0, __shfl_xor_sync(0xffffffffu, mA0, 2));
            mA1 = fmaxf(mA1, __shfl_xor_sync(0xffffffffu, mA1, 1));
            mA1 = fmaxf(mA1, __shfl_xor_sync(0xffffffffu, mA1, 2));
            mB0 = fmaxf(mB0, __shfl_xor_sync(0xffffffffu, mB0, 1));
            mB0 = fmaxf(mB0, __shfl_xor_sync(0xffffffffu, mB0, 2));
            mB1 = fmaxf(mB1, __shfl_xor_sync(0xffffffffu, mB1, 1));
            mB1 = fmaxf(mB1, __shfl_xor_sync(0xffffffffu, mB1, 2));

            if (tg == 0) {
                int posA = rg * 16 + gr;                        // posB = posA + 8
                size_t ba = (size_t)(pbase + posA) * 512 + t * 4 + nh * 2;
                *(float2*)&g_tmax[ba] = make_float2(mA0, mA1);
                size_t bbx = ba + (size_t)8 * 512;
                *(float2*)&g_tmax[bbx] = make_float2(mB0, mB1);
            }
        }
    }
}

// ---------------------------------------------------------------------------
// K_pass2: per position, scan 512 entry maxima -> top-2 entries;
// exact fp32 rescore of their 64 codes (cooperative row loads);
// write argmax + histogram. One warp per position; 8 positions per block.
// ---------------------------------------------------------------------------
__global__ __launch_bounds__(256) void k_pass2() {
    __shared__ float zs[8][32];
    int tid  = threadIdx.x;
    int wp   = tid >> 5;
    int lane = tid & 31;
    int p    = blockIdx.x * 8 + wp;

    zs[wp][lane] = g_z[(size_t)p * Dd + lane];
    __syncwarp();

    // ---- top-2 entries (approx values, tie -> smaller entry id) ----
    const float4* tm = (const float4*)(g_tmax + (size_t)p * 512 + lane * 16);
    float v1 = -3e38f, v2 = -3e38f;
    int   e1 = 0, e2 = 0;
    #pragma unroll
    for (int qq = 0; qq < 4; qq++) {
        float4 f = tm[qq];
        float vv[4] = {f.x, f.y, f.z, f.w};
        #pragma unroll
        for (int j = 0; j < 4; j++) {
            int ei = lane * 16 + qq * 4 + j;
            if (vv[j] > v2) {
                if (vv[j] > v1) { v2 = v1; e2 = e1; v1 = vv[j]; e1 = ei; }
                else            { v2 = vv[j]; e2 = ei; }
            }
        }
    }
    #pragma unroll
    for (int o = 16; o; o >>= 1) {
        float ov1 = __shfl_xor_sync(0xffffffffu, v1, o);
        int   oe1 = __shfl_xor_sync(0xffffffffu, e1, o);
        float ov2 = __shfl_xor_sync(0xffffffffu, v2, o);
        int   oe2 = __shfl_xor_sync(0xffffffffu, e2, o);
        if (better(ov1, oe1, v1, e1)) {
            if (better(v1, e1, ov2, oe2)) { v2 = v1; e2 = e1; }
            else                          { v2 = ov2; e2 = oe2; }
            v1 = ov1; e1 = oe1;
        } else if (better(ov1, oe1, v2, e2)) { v2 = ov1; e2 = oe1; }
    }

    // ---- exact rescore, cooperative: lane = (cg = lane>>2, qt = lane&3) ----
    int cg = lane >> 2, qt = lane & 3;
    float zq[8];
    #pragma unroll
    for (int j = 0; j < 8; j++) zq[j] = zs[wp][qt * 8 + j];

    float bv = -3e38f;
    int   bi = 0;
    #pragma unroll
    for (int it = 0; it < 8; it++) {
        int ee = (it < 4) ? e1 : e2;
        int c  = ee * 32 + (it & 3) * 8 + cg;
        const float4* er = (const float4*)(g_e + (size_t)c * Dd + qt * 8);
        float4 a = er[0], b = er[1];
        float s = a.x * zq[0] + a.y * zq[1] + a.z * zq[2] + a.w * zq[3]
                + b.x * zq[4] + b.y * zq[5] + b.z * zq[6] + b.w * zq[7];
        s += __shfl_xor_sync(0xffffffffu, s, 1);
        s += __shfl_xor_sync(0xffffffffu, s, 2);
        if (better(s, c, bv, bi)) { bv = s; bi = c; }
    }
    #pragma unroll
    for (int o = 16; o >= 4; o >>= 1) {
        float ov = __shfl_xor_sync(0xffffffffu, bv, o);
        int   oi = __shfl_xor_sync(0xffffffffu, bi, o);
        if (better(ov, oi, bv, bi)) { bv = ov; bi = oi; }
    }
    if (lane == 0) {
        g_idx[p] = bi;
        atomicAdd(&g_hist[bi], 1);
    }
}

// ---------------------------------------------------------------------------
// K3: gather latents, quantization-loss partial, expand D->C, write out.
// lat row hoisted into 32 regs; exp_s read via broadcast float4.
// ---------------------------------------------------------------------------
__global__ __launch_bounds__(256) void k_output(const float* __restrict__ ew,
                                                const float* __restrict__ eb,
                                                float* __restrict__ out) {
    __shared__ float lat_s[32][33];
    __shared__ float exp_s[64][32];
    __shared__ float red[256];

    int bh  = blockIdx.x;
    int b   = bh >> 5, h = bh & 31;
    int tid = threadIdx.x;
    int pbase = bh * 32;

    float lsum = 0.f;
    for (int i = tid; i < 1024; i += 256) {
        int ww = i >> 5, d = i & 31;
        int ix = g_idx[pbase + ww];
        float lv = g_e[(size_t)ix * Dd + d];
        lat_s[ww][d] = lv;
        float dz = g_z[((size_t)pbase + ww) * Dd + d] - lv;
        lsum += dz * dz;
    }
    red[tid] = lsum;
    __syncthreads();
    for (int s = 128; s; s >>= 1) {
        if (tid < s) red[tid] += red[tid + s];
        __syncthreads();
    }
    if (tid == 0) g_loss_part[bh] = red[0];

    int w   = tid & 31;
    int cg8 = tid >> 5;

    // hoist this thread's latent row (ready since the reduction barriers)
    float latr[32];
    #pragma unroll
    for (int d = 0; d < 32; d++) latr[d] = lat_s[w][d];

    for (int c0 = 0; c0 < Cc; c0 += 64) {
        __syncthreads();
        #pragma unroll
        for (int k = 0; k < 2; k++) {
            int i = tid + 256 * k;           // 0..511
            int cl = i >> 3, v = i & 7;
            *(float4*)&exp_s[cl][v * 4] =
                *(const float4*)(ew + (size_t)(c0 + cl) * Dd + v * 4);
        }
        __syncthreads();
        #pragma unroll
        for (int jj = 0; jj < 8; jj++) {
            int cl = cg8 + 8 * jj;
            int c  = c0 + cl;
            float s = eb[c];
            #pragma unroll
            for (int d4 = 0; d4 < 8; d4++) {
                float4 e4 = *(const float4*)&exp_s[cl][d4 * 4];
                s += e4.x * latr[4*d4] + e4.y * latr[4*d4+1]
                   + e4.z * latr[4*d4+2] + e4.w * latr[4*d4+3];
            }
            out[(((size_t)b * Cc + c) * Hh + h) * Ww + w] = s;
        }
    }
}

// ---------------------------------------------------------------------------
// K4: final scalars — loss mean and perplexity.
// ---------------------------------------------------------------------------
__global__ void k_scalars(float* __restrict__ out, int osz) {
    __shared__ float red[256];
    int tid = threadIdx.x;

    float s = 0.f;
    for (int i = tid; i < 512; i += 256) s += g_loss_part[i];
    red[tid] = s;
    __syncthreads();
    for (int st = 128; st; st >>= 1) {
        if (tid < st) red[tid] += red[tid + st];
        __syncthreads();
    }
    if (tid == 0) out[osz - 2] = red[0] / (float)(Pp * Dd);
    __syncthreads();

    float e = 0.f;
    const float inv = 1.0f / (float)Pp;
    for (int i = tid; i < Nn; i += 256) {
        int c = g_hist[i];
        if (c > 0) {
            float u = (float)c * inv;
            e -= u * logf(u + 1e-6f);
        }
    }
    red[tid] = e;
    __syncthreads();
    for (int st = 128; st; st >>= 1) {
        if (tid < st) red[tid] += red[tid + st];
        __syncthreads();
    }
    if (tid == 0) out[osz - 1] = expf(red[0]);
}

// ---------------------------------------------------------------------------
extern "C" void kernel_launch(void* const* d_in, const int* in_sizes, int n_in,
                              void* d_out, int out_size) {
    const float* enc = (const float*)d_in[0];   // encodings [B,C,H,W]
    const float* emb = (const float*)d_in[1];   // emb_weight [N,D]
    const float* pw  = (const float*)d_in[2];   // proj_w [D,C]
    const float* pb  = (const float*)d_in[3];   // proj_b [D]
    const float* ew  = (const float*)d_in[4];   // exp_w [C,D]
    const float* eb  = (const float*)d_in[5];   // exp_b [C]
    float* out = (float*)d_out;

    cudaFuncSetAttribute(k_sims, cudaFuncAttributeMaxDynamicSharedMemorySize, SIMS_SMEM);

    k_zero_hist<<<Nn / 256, 256>>>();
    k_prep_e<<<Nn / 8, 256>>>(emb);
    k_project<<<Bb * Hh, 256>>>(enc, pw, pb);
    k_sims<<<Pp / 64, 256, SIMS_SMEM>>>();
    k_pass2<<<Pp / 8, 256>>>();
    k_output<<<Bb * Hh, 256>>>(ew, eb, out);
    k_scalars<<<1, 256>>>(out, out_size);
}

// round 12
// speedup vs baseline: 1.5973x; 1.5973x over previous
#include <cuda_runtime.h>
#include <cuda_fp16.h>
#include <math.h>
#include <cstdint>

#define Bb 16
#define Cc 512
#define Hh 32
#define Ww 32
#define Nn 16384
#define Dd 32
#define Pp 16384   // Bb*Hh*Ww

// ---------------------------------------------------------------------------
// Scratch (__device__ globals; no allocation allowed)
// ---------------------------------------------------------------------------
__device__ float g_z[Pp * Dd];        // normalized projected latents [p][d]
__device__ float g_e[Nn * Dd];        // normalized codebook fp32 [n][d] (rows 128B aligned)
__device__ uint4 g_eb[Nn * 4];        // codebook fp16: [n][32 half] = 64 B/row
__device__ float g_tmax[(size_t)Pp * 512];  // per-position per-32-code-entry max (fp16 sims)
__device__ int   g_idx[Pp];
__device__ int   g_hist[Nn];
__device__ float g_loss_part[512];

// ---------------------------------------------------------------------------
// PTX helpers (baseline PTX only: no 'a'-features)
// ---------------------------------------------------------------------------
__device__ __forceinline__ uint32_t smem_u32(const void* p) {
    uint32_t a;
    asm("{ .reg .u64 t; cvta.to.shared.u64 t, %1; cvt.u32.u64 %0, t; }" : "=r"(a) : "l"(p));
    return a;
}
__device__ __forceinline__ void ldsm4(uint32_t* r, uint32_t addr) {
    asm volatile("ldmatrix.sync.aligned.m8n8.x4.shared.b16 {%0,%1,%2,%3}, [%4];"
                 : "=r"(r[0]), "=r"(r[1]), "=r"(r[2]), "=r"(r[3]) : "r"(addr));
}
__device__ __forceinline__ void mma16816(float* d, const uint32_t* a, const uint32_t* b) {
    asm volatile("mma.sync.aligned.m16n8k16.row.col.f32.f16.f16.f32 "
                 "{%0,%1,%2,%3}, {%4,%5,%6,%7}, {%8,%9}, {%0,%1,%2,%3};"
                 : "+f"(d[0]), "+f"(d[1]), "+f"(d[2]), "+f"(d[3])
                 : "r"(a[0]), "r"(a[1]), "r"(a[2]), "r"(a[3]), "r"(b[0]), "r"(b[1]));
}
__device__ __forceinline__ void cpasync16(uint32_t dst, const void* src) {
    asm volatile("cp.async.cg.shared.global [%0], [%1], 16;" :: "r"(dst), "l"(src));
}
#define CP_COMMIT() asm volatile("cp.async.commit_group;" ::: "memory")
#define CP_WAIT0()  asm volatile("cp.async.wait_group 0;" ::: "memory")
#define CP_WAIT1()  asm volatile("cp.async.wait_group 1;" ::: "memory")

__device__ __forceinline__ bool better(float xv, int xi, float yv, int yi) {
    return xv > yv || (xv == yv && xi < yi);
}

// ---------------------------------------------------------------------------
// K_zero: clear histogram (keeps k_sims in the ncu capture slot)
// ---------------------------------------------------------------------------
__global__ void k_zero_hist() {
    g_hist[blockIdx.x * 256 + threadIdx.x] = 0;
}

// ---------------------------------------------------------------------------
// K_prep_e: normalize codebook rows; fp32 copy + single fp16 copy.
// ---------------------------------------------------------------------------
__global__ void k_prep_e(const float* __restrict__ emb) {
    int warp = threadIdx.x >> 5, lane = threadIdx.x & 31;
    int n = blockIdx.x * 8 + warp;
    float v = emb[n * Dd + lane];
    float ss = v * v;
    #pragma unroll
    for (int o = 16; o; o >>= 1) ss += __shfl_xor_sync(0xffffffffu, ss, o);
    float rn = 1.0f / fmaxf(sqrtf(ss), 1e-6f);
    float zn = v * rn;
    g_e[n * Dd + lane] = zn;
    ((__half*)g_eb)[(size_t)n * 32 + lane] = __float2half(zn);
}

// ---------------------------------------------------------------------------
// K1: projection (1x1 conv C->D) + L2 normalize along D.
// ---------------------------------------------------------------------------
__global__ __launch_bounds__(256) void k_project(const float* __restrict__ enc,
                                                 const float* __restrict__ pw,
                                                 const float* __restrict__ pb) {
    __shared__ float enc_s[64][32];
    __shared__ float proj_s[32][64];
    __shared__ float z_s[32][33];
    __shared__ float rn_s[32];

    int bh  = blockIdx.x;
    int tid = threadIdx.x;
    int w   = tid & 31;
    int dg  = tid >> 5;

    const float* encbase = enc + (size_t)(bh >> 5) * Cc * Hh * Ww + (size_t)(bh & 31) * Ww;

    float acc[4] = {0.f, 0.f, 0.f, 0.f};

    for (int c0 = 0; c0 < Cc; c0 += 64) {
        #pragma unroll
        for (int k = 0; k < 2; k++) {
            int i = tid + 256 * k;            // 0..511
            int cl = i >> 3, v = i & 7;
            *(float4*)&enc_s[cl][v * 4] =
                *(const float4*)(encbase + (size_t)(c0 + cl) * (Hh * Ww) + v * 4);
        }
        #pragma unroll
        for (int k = 0; k < 2; k++) {
            int i = tid + 256 * k;
            int d = i >> 4, c4 = i & 15;
            *(float4*)&proj_s[d][c4 * 4] =
                *(const float4*)(pw + d * Cc + c0 + c4 * 4);
        }
        __syncthreads();
        #pragma unroll 16
        for (int cl = 0; cl < 64; cl++) {
            float ev = enc_s[cl][w];
            #pragma unroll
            for (int j = 0; j < 4; j++) acc[j] += proj_s[dg + 8 * j][cl] * ev;
        }
        __syncthreads();
    }
    #pragma unroll
    for (int j = 0; j < 4; j++) z_s[dg + 8 * j][w] = acc[j] + pb[dg + 8 * j];
    __syncthreads();

    if (tid < 32) {
        float ss = 0.f;
        #pragma unroll
        for (int d = 0; d < 32; d++) { float v = z_s[d][tid]; ss += v * v; }
        rn_s[tid] = 1.0f / fmaxf(sqrtf(ss), 1e-6f);
    }
    __syncthreads();

    for (int i = tid; i < 1024; i += 256) {
        int ww = i >> 5, d = i & 31;
        g_z[((size_t)bh * 32 + ww) * Dd + d] = z_s[d][ww] * rn_s[ww];
    }
}

// ---------------------------------------------------------------------------
// K2: single-term fp16 HMMA sims (K=32); per-position per-32-code-entry MAX.
// fp16 sim error <= ~2^-10 * sum|z_d e_d| (worst ~7e-4); pass2 rescores the
// top-4 entries (128 codes) in exact fp32 to absorb it.
// CTA: 256 threads (8 warps), 64 positions; 2 CTAs/SM. Code tile = 128.
// Warp: rg = w&3 (16 positions), nh = w>>2 (64 codes).
// Round-10 proven loop: 3 B buffers, CP_WAIT1, one barrier per tile.
// Rows 64 B, smem stride 80 B (5x16 -> conflict-free LDSM).
// ---------------------------------------------------------------------------
#define A_BYTES   5120                        // 64 * 80
#define B_BYTES   10240                       // 128 * 80
#define SIMS_SMEM (A_BYTES + 3 * B_BYTES)     // 35840

__global__ __launch_bounds__(256, 2) void k_sims() {
    extern __shared__ __align__(16) char sm[];
    __half* As = (__half*)sm;                 // stride 40 half = 80 B
    uint32_t sbase = smem_u32(sm);

    int tid  = threadIdx.x;
    int lane = tid & 31;
    int w    = tid >> 5;      // 0..7
    int rg   = w & 3;         // row group (16 positions)
    int nh   = w >> 2;        // n-half (64 codes)
    int tg   = lane & 3;
    int gr   = lane >> 2;     // row-in-group 0..7
    int pbase = blockIdx.x * 64;

    // ---- build A tile: fp16 z (64 rows, 80 B stride) ----
    for (int i = tid; i < 64 * 32; i += 256) {
        int row = i >> 5, d = i & 31;
        As[row * 40 + d] = __float2half(g_z[(size_t)(pbase + row) * Dd + d]);
    }

    // ---- cp.async addressing: row = tid>>1, 2 chunks of 16B per thread ----
    // B tile = 128 codes x 64 B; 2 threads per row.
    uint32_t cprow = (uint32_t)(tid >> 1);
    uint32_t cphalf = (uint32_t)((tid & 1) * 32);
    uint32_t srcBase = cprow * 64 + cphalf;
    uint32_t dstBase = cprow * 80 + cphalf;

    // ---- prefetch B tiles 0 and 1 ----
    const char* ebase = (const char*)g_eb;
    #pragma unroll
    for (int j = 0; j < 2; j++)
        cpasync16(sbase + A_BYTES + dstBase + j * 16, ebase + srcBase + j * 16);
    CP_COMMIT();
    #pragma unroll
    for (int j = 0; j < 2; j++)
        cpasync16(sbase + A_BYTES + B_BYTES + dstBase + j * 16,
                  ebase + 8192 + srcBase + j * 16);
    CP_COMMIT();
    __syncthreads();

    // ---- A fragments: 2 k-steps, hoisted (8 regs) ----
    uint32_t afr[2][4];
    int q = lane >> 3, r = lane & 7;
    {
        uint32_t abase = sbase + (uint32_t)((rg * 16 + (q & 1) * 8 + r) * 80
                                            + (q >> 1) * 16);
        #pragma unroll
        for (int kk = 0; kk < 2; kk++) ldsm4(afr[kk], abase + kk * 32);
    }
    uint32_t brow_off = (uint32_t)((nh * 64 + (q >> 1) * 8 + r) * 80 + (q & 1) * 16);

    for (int t = 0; t < 128; t++) {
        if (t < 126) CP_WAIT1(); else CP_WAIT0();
        __syncthreads();
        if (t + 2 < 128) {
            const char* src = ebase + (size_t)(t + 2) * 8192 + srcBase;
            uint32_t dst = sbase + A_BYTES + (uint32_t)(((t + 2) % 3) * B_BYTES) + dstBase;
            #pragma unroll
            for (int j = 0; j < 2; j++)
                cpasync16(dst + j * 16, src + j * 16);
            CP_COMMIT();
        }

        uint32_t bb = sbase + A_BYTES + (uint32_t)((t % 3) * B_BYTES) + brow_off;
        float acc[8][4];
        #pragma unroll
        for (int nb = 0; nb < 8; nb++)
            #pragma unroll
            for (int i = 0; i < 4; i++) acc[nb][i] = 0.f;

        #pragma unroll
        for (int j = 0; j < 4; j++) {          // four n16 groups
            uint32_t bbj = bb + (uint32_t)j * (16 * 80);
            uint32_t b0[4], b1[4];
            ldsm4(b0, bbj);                    // k-step 0
            ldsm4(b1, bbj + 32);               // k-step 1
            mma16816(acc[2*j],   afr[0], b0); mma16816(acc[2*j+1], afr[0], b0 + 2);
            mma16816(acc[2*j],   afr[1], b1); mma16816(acc[2*j+1], afr[1], b1 + 2);
        }

        // ---- per-entry max (value only, FMNMX trees + shfl) ----
        // acc 0..3 = codes nh*64+0..31 (entry t*4+nh*2), acc 4..7 = +32..63.
        float mA0, mA1, mB0, mB1;
        {
            float a0 = fmaxf(fmaxf(acc[0][0], acc[0][1]), fmaxf(acc[1][0], acc[1][1]));
            float a1 = fmaxf(fmaxf(acc[2][0], acc[2][1]), fmaxf(acc[3][0], acc[3][1]));
            mA0 = fmaxf(a0, a1);
            float a2 = fmaxf(fmaxf(acc[4][0], acc[4][1]), fmaxf(acc[5][0], acc[5][1]));
            float a3 = fmaxf(fmaxf(acc[6][0], acc[6][1]), fmaxf(acc[7][0], acc[7][1]));
            mA1 = fmaxf(a2, a3);
            float b0 = fmaxf(fmaxf(acc[0][2], acc[0][3]), fmaxf(acc[1][2], acc[1][3]));
            float b1 = fmaxf(fmaxf(acc[2][2], acc[2][3]), fmaxf(acc[3][2], acc[3][3]));
            mB0 = fmaxf(b0, b1);
            float b2 = fmaxf(fmaxf(acc[4][2], acc[4][3]), fmaxf(acc[5][2], acc[5][3]));
            float b3 = fmaxf(fmaxf(acc[6][2], acc[6][3]), fmaxf(acc[7][2], acc[7][3]));
            mB1 = fmaxf(b2, b3);
        }
        mA0 = fmaxf(mA0, __shfl_xor_sync(0xffffffffu, mA0, 1));
        mA0 = fmaxf(mA0, __shfl_xor_sync(0xffffffffu, mA0, 2));
        mA1 = fmaxf(mA1, __shfl_xor_sync(0xffffffffu, mA1, 1));
        mA1 = fmaxf(mA1, __shfl_xor_sync(0xffffffffu, mA1, 2));
        mB0 = fmaxf(mB0, __shfl_xor_sync(0xffffffffu, mB0, 1));
        mB0 = fmaxf(mB0, __shfl_xor_sync(0xffffffffu, mB0, 2));
        mB1 = fmaxf(mB1, __shfl_xor_sync(0xffffffffu, mB1, 1));
        mB1 = fmaxf(mB1, __shfl_xor_sync(0xffffffffu, mB1, 2));

        if (tg == 0) {
            int posA = rg * 16 + gr;                        // posB = posA + 8
            size_t ba = (size_t)(pbase + posA) * 512 + t * 4 + nh * 2;
            *(float2*)&g_tmax[ba] = make_float2(mA0, mA1);
            size_t bbx = ba + (size_t)8 * 512;
            *(float2*)&g_tmax[bbx] = make_float2(mB0, mB1);
        }
    }
}

// ---------------------------------------------------------------------------
// K_pass2: per position, scan 512 entry maxima -> TOP-4 entries;
// exact fp32 rescore of their 128 codes (cooperative row loads);
// write argmax + histogram. One warp per position; 8 positions per block.
// ---------------------------------------------------------------------------
__global__ __launch_bounds__(256) void k_pass2() {
    __shared__ float zs[8][32];
    int tid  = threadIdx.x;
    int wp   = tid >> 5;
    int lane = tid & 31;
    int p    = blockIdx.x * 8 + wp;

    zs[wp][lane] = g_z[(size_t)p * Dd + lane];
    __syncwarp();

    // ---- load this lane's 16 entry maxima ----
    const float4* tm = (const float4*)(g_tmax + (size_t)p * 512 + lane * 16);
    float ev[16];
    #pragma unroll
    for (int qq = 0; qq < 4; qq++) {
        float4 f = tm[qq];
        ev[qq * 4 + 0] = f.x; ev[qq * 4 + 1] = f.y;
        ev[qq * 4 + 2] = f.z; ev[qq * 4 + 3] = f.w;
    }

    // ---- top-4 entries via 4 masked warp-max rounds (tie -> smaller id) ----
    int sel[4];
    #pragma unroll
    for (int rr = 0; rr < 4; rr++) {
        float bvv = -3e38f; int be = 0x7fffffff;
        #pragma unroll
        for (int j = 0; j < 16; j++)
            if (better(ev[j], lane * 16 + j, bvv, be)) { bvv = ev[j]; be = lane * 16 + j; }
        #pragma unroll
        for (int o = 16; o; o >>= 1) {
            float ovv = __shfl_xor_sync(0xffffffffu, bvv, o);
            int   oee = __shfl_xor_sync(0xffffffffu, be, o);
            if (better(ovv, oee, bvv, be)) { bvv = ovv; be = oee; }
        }
        sel[rr] = be;
        #pragma unroll
        for (int j = 0; j < 16; j++)
            if (lane * 16 + j == be) ev[j] = -3e38f;
    }

    // ---- exact rescore, cooperative: lane = (cg = lane>>2, qt = lane&3) ----
    int cg = lane >> 2, qt = lane & 3;
    float zq[8];
    #pragma unroll
    for (int j = 0; j < 8; j++) zq[j] = zs[wp][qt * 8 + j];

    float bv = -3e38f;
    int   bi = 0;
    #pragma unroll
    for (int it = 0; it < 16; it++) {
        int ee = sel[it >> 2];
        int c  = ee * 32 + (it & 3) * 8 + cg;
        const float4* er = (const float4*)(g_e + (size_t)c * Dd + qt * 8);
        float4 a = er[0], b = er[1];
        float s = a.x * zq[0] + a.y * zq[1] + a.z * zq[2] + a.w * zq[3]
                + b.x * zq[4] + b.y * zq[5] + b.z * zq[6] + b.w * zq[7];
        s += __shfl_xor_sync(0xffffffffu, s, 1);
        s += __shfl_xor_sync(0xffffffffu, s, 2);
        if (better(s, c, bv, bi)) { bv = s; bi = c; }
    }
    #pragma unroll
    for (int o = 16; o >= 4; o >>= 1) {
        float ov = __shfl_xor_sync(0xffffffffu, bv, o);
        int   oi = __shfl_xor_sync(0xffffffffu, bi, o);
        if (better(ov, oi, bv, bi)) { bv = ov; bi = oi; }
    }
    if (lane == 0) {
        g_idx[p] = bi;
        atomicAdd(&g_hist[bi], 1);
    }
}

// ---------------------------------------------------------------------------
// K3: gather latents, quantization-loss partial, expand D->C, write out.
// ---------------------------------------------------------------------------
__global__ __launch_bounds__(256) void k_output(const float* __restrict__ ew,
                                                const float* __restrict__ eb,
                                                float* __restrict__ out) {
    __shared__ float lat_s[32][33];
    __shared__ float exp_s[64][32];
    __shared__ float red[256];

    int bh  = blockIdx.x;
    int b   = bh >> 5, h = bh & 31;
    int tid = threadIdx.x;
    int pbase = bh * 32;

    float lsum = 0.f;
    for (int i = tid; i < 1024; i += 256) {
        int ww = i >> 5, d = i & 31;
        int ix = g_idx[pbase + ww];
        float lv = g_e[(size_t)ix * Dd + d];
        lat_s[ww][d] = lv;
        float dz = g_z[((size_t)pbase + ww) * Dd + d] - lv;
        lsum += dz * dz;
    }
    red[tid] = lsum;
    __syncthreads();
    for (int s = 128; s; s >>= 1) {
        if (tid < s) red[tid] += red[tid + s];
        __syncthreads();
    }
    if (tid == 0) g_loss_part[bh] = red[0];

    int w   = tid & 31;
    int cg8 = tid >> 5;

    float latr[32];
    #pragma unroll
    for (int d = 0; d < 32; d++) latr[d] = lat_s[w][d];

    for (int c0 = 0; c0 < Cc; c0 += 64) {
        __syncthreads();
        #pragma unroll
        for (int k = 0; k < 2; k++) {
            int i = tid + 256 * k;           // 0..511
            int cl = i >> 3, v = i & 7;
            *(float4*)&exp_s[cl][v * 4] =
                *(const float4*)(ew + (size_t)(c0 + cl) * Dd + v * 4);
        }
        __syncthreads();
        #pragma unroll
        for (int jj = 0; jj < 8; jj++) {
            int cl = cg8 + 8 * jj;
            int c  = c0 + cl;
            float s = eb[c];
            #pragma unroll
            for (int d4 = 0; d4 < 8; d4++) {
                float4 e4 = *(const float4*)&exp_s[cl][d4 * 4];
                s += e4.x * latr[4*d4] + e4.y * latr[4*d4+1]
                   + e4.z * latr[4*d4+2] + e4.w * latr[4*d4+3];
            }
            out[(((size_t)b * Cc + c) * Hh + h) * Ww + w] = s;
        }
    }
}

// ---------------------------------------------------------------------------
// K4: final scalars — loss mean and perplexity.
// ---------------------------------------------------------------------------
__global__ void k_scalars(float* __restrict__ out, int osz) {
    __shared__ float red[256];
    int tid = threadIdx.x;

    float s = 0.f;
    for (int i = tid; i < 512; i += 256) s += g_loss_part[i];
    red[tid] = s;
    __syncthreads();
    for (int st = 128; st; st >>= 1) {
        if (tid < st) red[tid] += red[tid + st];
        __syncthreads();
    }
    if (tid == 0) out[osz - 2] = red[0] / (float)(Pp * Dd);
    __syncthreads();

    float e = 0.f;
    const float inv = 1.0f / (float)Pp;
    for (int i = tid; i < Nn; i += 256) {
        int c = g_hist[i];
        if (c > 0) {
            float u = (float)c * inv;
            e -= u * logf(u + 1e-6f);
        }
    }
    red[tid] = e;
    __syncthreads();
    for (int st = 128; st; st >>= 1) {
        if (tid < st) red[tid] += red[tid + st];
        __syncthreads();
    }
    if (tid == 0) out[osz - 1] = expf(red[0]);
}

// ---------------------------------------------------------------------------
extern "C" void kernel_launch(void* const* d_in, const int* in_sizes, int n_in,
                              void* d_out, int out_size) {
    const float* enc = (const float*)d_in[0];   // encodings [B,C,H,W]
    const float* emb = (const float*)d_in[1];   // emb_weight [N,D]
    const float* pw  = (const float*)d_in[2];   // proj_w [D,C]
    const float* pb  = (const float*)d_in[3];   // proj_b [D]
    const float* ew  = (const float*)d_in[4];   // exp_w [C,D]
    const float* eb  = (const float*)d_in[5];   // exp_b [C]
    float* out = (float*)d_out;

    cudaFuncSetAttribute(k_sims, cudaFuncAttributeMaxDynamicSharedMemorySize, SIMS_SMEM);

    k_zero_hist<<<Nn / 256, 256>>>();
    k_prep_e<<<Nn / 8, 256>>>(emb);
    k_project<<<Bb * Hh, 256>>>(enc, pw, pb);
    k_sims<<<Pp / 64, 256, SIMS_SMEM>>>();
    k_pass2<<<Pp / 8, 256>>>();
    k_output<<<Bb * Hh, 256>>>(ew, eb, out);
    k_scalars<<<1, 256>>>(out, out_size);
}